// round 2
// baseline (speedup 1.0000x reference)
#include <cuda_runtime.h>
#include <cstdint>
#include <math.h>

#define TSTEPS 4096
#define DIN    512
#define FDIM   256
#define HID    200
#define G4     800
#define KDIM   40
#define NSLOT  128
#define EPSF   1e-12f
#define CLSZ   8
#define JPC    25     // hidden units per CTA
#define RPC    100    // gate rows per CTA

// ---------------- scratch (device globals) ----------------
__device__ float g_xs[TSTEPS * FDIM];
__device__ float g_gx[TSTEPS * G4];
__device__ float g_hid[TSTEPS * HID];
__device__ float g_WinT[FDIM * DIN];
__device__ float g_Wx[G4 * FDIM];
__device__ float g_wy[G4];
__device__ float g_bsum[G4];
__device__ unsigned g_flag[8];

// ---------------- helpers ----------------
__device__ __forceinline__ float fsigmoid(float x) {
    return __fdividef(1.f, 1.f + __expf(-x));
}
__device__ __forceinline__ float ftanh(float x) {
    float a = fabsf(x);
    float e = __expf(-2.f * a);
    float r = __fdividef(1.f - e, 1.f + e);
    return copysignf(r, x);
}
__device__ __forceinline__ uint32_t smem_u32(const void* p) {
    return (uint32_t)__cvta_generic_to_shared(p);
}
__device__ __forceinline__ uint32_t my_cluster_rank() {
    uint32_t r; asm("mov.u32 %0, %%cluster_ctarank;" : "=r"(r)); return r;
}
__device__ __forceinline__ uint32_t mapa_u32(uint32_t laddr, uint32_t rank) {
    uint32_t r;
    asm("mapa.shared::cluster.u32 %0, %1, %2;" : "=r"(r) : "r"(laddr), "r"(rank));
    return r;
}
__device__ __forceinline__ void cluster_sync_() {
    asm volatile("barrier.cluster.arrive.aligned;" ::: "memory");
    asm volatile("barrier.cluster.wait.aligned;" ::: "memory");
}
__device__ __forceinline__ void mbar_init(uint32_t addr, uint32_t cnt) {
    asm volatile("mbarrier.init.shared.b64 [%0], %1;" :: "r"(addr), "r"(cnt) : "memory");
}
__device__ __forceinline__ void mbar_expect_tx(uint32_t addr, uint32_t bytes) {
    asm volatile("mbarrier.arrive.expect_tx.shared.b64 _, [%0], %1;"
                 :: "r"(addr), "r"(bytes) : "memory");
}
__device__ __forceinline__ void mbar_arrive_remote(uint32_t raddr) {
    asm volatile("mbarrier.arrive.release.cluster.shared::cluster.b64 _, [%0];"
                 :: "r"(raddr) : "memory");
}
__device__ __forceinline__ void mbar_wait(uint32_t addr, uint32_t parity) {
    asm volatile(
        "{\n\t.reg .pred P;\n\t"
        "WL_%=:\n\t"
        "mbarrier.try_wait.parity.acquire.cluster.shared::cta.b64 P, [%0], %1, 0x989680;\n\t"
        "@!P bra WL_%=;\n\t}"
        :: "r"(addr), "r"(parity) : "memory");
}
__device__ __forceinline__ void st_async_f32(uint32_t raddr, float v, uint32_t rmbar) {
    asm volatile("st.async.shared::cluster.mbarrier::complete_tx::bytes.u32 [%0], %1, [%2];"
                 :: "r"(raddr), "r"(__float_as_uint(v)), "r"(rmbar) : "memory");
}

// ---------------- prep ----------------
__global__ void prep_kernel(const float* __restrict__ W_in, const float* __restrict__ W_ih,
                            const float* __restrict__ b_ih, const float* __restrict__ b_hh) {
    int idx = blockIdx.x * blockDim.x + threadIdx.x;
    if (idx < G4 * FDIM) {
        int n = idx / FDIM, k = idx % FDIM;
        g_Wx[idx] = W_ih[n * (FDIM + 1) + k];
    }
    if (idx < DIN * FDIM) {
        int k = idx / FDIM, n = idx % FDIM;
        g_WinT[n * DIN + k] = W_in[idx];
    }
    if (idx < G4) {
        g_wy[idx]   = W_ih[idx * (FDIM + 1) + FDIM];
        g_bsum[idx] = b_ih[idx] + b_hh[idx];
    }
    if (idx < 8) g_flag[idx] = 0;
}

// ---------------- GEMM C = A * B^T ----------------
__device__ __forceinline__ void gemm_nt_body(
    const float* __restrict__ A, const float* __restrict__ B, float* __restrict__ C,
    int M, int N, int K,
    const float* __restrict__ bias, const float* __restrict__ yvec, const float* __restrict__ wy)
{
    __shared__ __align__(16) float As[16][64];
    __shared__ __align__(16) float Bs[16][64];
    const int m0 = blockIdx.y * 64, n0 = blockIdx.x * 64;
    const int tid = threadIdx.x;
    const int tx = tid % 16, ty = tid / 16;
    const int lr = tid / 4, lc4 = (tid % 4) * 4;

    float acc[4][4];
#pragma unroll
    for (int i = 0; i < 4; i++)
#pragma unroll
        for (int j = 0; j < 4; j++) acc[i][j] = 0.f;

    for (int k0 = 0; k0 < K; k0 += 16) {
        float4 av = *reinterpret_cast<const float4*>(A + (size_t)(m0 + lr) * K + k0 + lc4);
        As[lc4 + 0][lr] = av.x; As[lc4 + 1][lr] = av.y;
        As[lc4 + 2][lr] = av.z; As[lc4 + 3][lr] = av.w;
        float4 bv = make_float4(0.f, 0.f, 0.f, 0.f);
        if (n0 + lr < N) bv = *reinterpret_cast<const float4*>(B + (size_t)(n0 + lr) * K + k0 + lc4);
        Bs[lc4 + 0][lr] = bv.x; Bs[lc4 + 1][lr] = bv.y;
        Bs[lc4 + 2][lr] = bv.z; Bs[lc4 + 3][lr] = bv.w;
        __syncthreads();
#pragma unroll
        for (int kk = 0; kk < 16; kk++) {
            float4 a4 = *reinterpret_cast<const float4*>(&As[kk][ty * 4]);
            float4 b4 = *reinterpret_cast<const float4*>(&Bs[kk][tx * 4]);
            float aa[4] = {a4.x, a4.y, a4.z, a4.w};
            float bb[4] = {b4.x, b4.y, b4.z, b4.w};
#pragma unroll
            for (int i = 0; i < 4; i++)
#pragma unroll
                for (int j = 0; j < 4; j++) acc[i][j] = fmaf(aa[i], bb[j], acc[i][j]);
        }
        __syncthreads();
    }
#pragma unroll
    for (int i = 0; i < 4; i++) {
        int m = m0 + ty * 4 + i;
        float yv = 0.f;
        if (yvec) yv = (m == 0) ? 0.f : yvec[m - 1];
#pragma unroll
        for (int j = 0; j < 4; j++) {
            int n = n0 + tx * 4 + j;
            if (n < N) {
                float v = acc[i][j] + (bias ? bias[n] : 0.f);
                if (wy) v = fmaf(yv, wy[n], v);
                C[(size_t)m * N + n] = v;
            }
        }
    }
}

__global__ void __launch_bounds__(256) gemm1_kernel(const float* __restrict__ x,
                                                    const float* __restrict__ b_in) {
    gemm_nt_body(x, g_WinT, g_xs, TSTEPS, FDIM, DIN, b_in, nullptr, nullptr);
}
__global__ void __launch_bounds__(256) gemm2_kernel(const float* __restrict__ y) {
    gemm_nt_body(g_xs, g_Wx, g_gx, TSTEPS, G4, FDIM, g_bsum, y, g_wy);
}

// ---------------- fused LSTM (cluster of 8) + keys + MANN (CTA 8) ----------------
struct LstmShm {
    float h[2][HID];
    float part[RPC];
    float gate[RPC];
    unsigned long long full;
    unsigned long long empty[2];
};
struct MannShm {
    float Wk[HID * KDIM];
    float Ws[HID];
    float bk[KDIM];
    float hsh[HID];
    float key[KDIM];
    float kn[KDIM];
    float wsum[4];
    float sig;
    float bs;
};

__global__ void __cluster_dims__(CLSZ, 1, 1) __launch_bounds__(256, 1)
fused_kernel(const float* __restrict__ W_hh,
             const float* __restrict__ W_k, const float* __restrict__ b_k,
             const float* __restrict__ W_s, const float* __restrict__ b_s,
             float* __restrict__ out)
{
    __shared__ __align__(16) LstmShm L;
    __shared__ __align__(16) MannShm S;

    const int tid = threadIdx.x;

    if (blockIdx.x < CLSZ) {
        // =============== LSTM cluster ===============
        const uint32_t rank = my_cluster_rank();
        const bool act = tid < 2 * RPC;
        const int rl  = tid % RPC;          // local gate row 0..99 (valid if act)
        const int cc  = tid / RPC;          // k-half 0/1
        const int gate = rl / JPC, jj = rl % JPC;
        const int grow = gate * HID + (int)rank * JPC + jj;

        float4 w4[25];
        if (act) {
            const float4* wp = reinterpret_cast<const float4*>(W_hh + (size_t)grow * HID + cc * 100);
#pragma unroll
            for (int q = 0; q < 25; q++) w4[q] = wp[q];
        }
        if (tid < HID) L.h[0][tid] = 0.f;

        const uint32_t fullA = smem_u32(&L.full);
        const uint32_t eA[2] = { smem_u32(&L.empty[0]), smem_u32(&L.empty[1]) };
        const uint32_t hA    = smem_u32(&L.h[0][0]);
        if (tid == 0) {
            mbar_init(fullA, 1);
            mbar_init(eA[0], CLSZ);
            mbar_init(eA[1], CLSZ);
        }
        uint32_t r_emp0 = 0, r_emp1 = 0;
        if (tid < CLSZ) {
            r_emp0 = mapa_u32(eA[0], (uint32_t)tid);
            r_emp1 = mapa_u32(eA[1], (uint32_t)tid);
        }
        uint32_t r_h[CLSZ], r_full[CLSZ];
        if (tid < JPC) {
#pragma unroll
            for (int p = 0; p < CLSZ; p++) {
                r_h[p]    = mapa_u32(hA, (uint32_t)p);
                r_full[p] = mapa_u32(fullA, (uint32_t)p);
            }
        }
        float cst = 0.f;
        __syncthreads();
        cluster_sync_();   // all peers' barriers initialized, h[0] zeroed

        float gxv = (act && cc == 0) ? g_gx[grow] : 0.f;

        for (int t = 0; t < TSTEPS; t++) {
            const int buf = t & 1, bw = buf ^ 1;

            float a0 = 0.f, a1 = 0.f, a2 = 0.f, a3 = 0.f;
            if (act) {
                const float4* h4 = reinterpret_cast<const float4*>(&L.h[buf][cc * 100]);
#pragma unroll
                for (int q = 0; q < 25; q++) {
                    float4 hv = h4[q], wv = w4[q];
                    a0 = fmaf(wv.x, hv.x, a0);
                    a1 = fmaf(wv.y, hv.y, a1);
                    a2 = fmaf(wv.z, hv.z, a2);
                    a3 = fmaf(wv.w, hv.w, a3);
                }
            }
            float gx_next = 0.f;
            if (act && cc == 0 && t + 1 < TSTEPS) gx_next = g_gx[(size_t)(t + 1) * G4 + grow];
            if (act) {
                float s = (a0 + a1) + (a2 + a3);
                if (cc) L.part[rl] = s;
                else    L.gate[rl] = s + gxv;
            }
            __syncthreads();
            // signal "my reads of buffer buf are done" to every CTA's empty[buf]
            if (tid < CLSZ) mbar_arrive_remote(buf ? r_emp1 : r_emp0);

            float h = 0.f;
            if (tid < JPC) {
                float gi = L.gate[tid]           + L.part[tid];
                float gf = L.gate[JPC + tid]     + L.part[JPC + tid];
                float gg = L.gate[2 * JPC + tid] + L.part[2 * JPC + tid];
                float go = L.gate[3 * JPC + tid] + L.part[3 * JPC + tid];
                float si = fsigmoid(gi), sf = fsigmoid(gf), so = fsigmoid(go);
                cst = sf * cst + si * ftanh(gg);
                h = so * ftanh(cst);
                g_hid[(size_t)t * HID + (int)rank * JPC + tid] = h;
            }
            gxv = gx_next;

            if (t + 1 < TSTEPS) {
                if (tid < JPC) {
                    if (t >= 1) mbar_wait(eA[bw], ((unsigned)(t - 1) >> 1) & 1u);
                    const uint32_t off = (uint32_t)(bw * HID + (int)rank * JPC + tid) * 4u;
#pragma unroll
                    for (int p = 0; p < CLSZ; p++) st_async_f32(r_h[p] + off, h, r_full[p]);
                }
                if (tid == 0) mbar_expect_tx(fullA, HID * 4);
            }
            // publish flag for the MANN consumer
            if (tid < JPC) {
                __syncwarp(0x01FFFFFFu);
                if (tid == 0) {
                    asm volatile("fence.acq_rel.gpu;" ::: "memory");
                    *((volatile unsigned*)&g_flag[rank]) = (unsigned)(t + 1);
                }
            }
            if (t + 1 < TSTEPS) mbar_wait(fullA, (unsigned)t & 1u);
        }
        return;
    }

    if (blockIdx.x != CLSZ) return;   // CTAs 9..15 idle

    // =============== keys + MANN consumer CTA ===============
    for (int i = tid; i < HID * KDIM; i += 256) S.Wk[i] = W_k[i];
    for (int i = tid; i < HID; i += 256) S.Ws[i] = W_s[i];
    if (tid < KDIM) S.bk[tid] = b_k[tid];
    if (tid == 0)   S.bs = b_s[0];

    float M[KDIM];
    float wr = 0.f;
    if (tid < NSLOT) {
#pragma unroll
        for (int d = 0; d < KDIM; d++) M[d] = 1e-6f;
        wr = (tid == 0) ? 1.f : 0.f;
    }
    __syncthreads();

    for (int t = 0; t < TSTEPS; t++) {
        if (tid == 0) {
            volatile unsigned* f = (volatile unsigned*)g_flag;
            for (;;) {
                unsigned mn = 0xffffffffu;
#pragma unroll
                for (int p = 0; p < CLSZ; p++) mn = min(mn, f[p]);
                if (mn > (unsigned)t) break;
            }
            asm volatile("fence.acq_rel.gpu;" ::: "memory");
        }
        __syncthreads();
        if (tid < HID) S.hsh[tid] = g_hid[(size_t)t * HID + tid];
        __syncthreads();

        if (tid < 4 * KDIM) {                 // keys: 4 threads per output
            const int k = tid >> 2, p = tid & 3;
            const float* wp = &S.Wk[(p * 50) * KDIM + k];
            const float* hp = &S.hsh[p * 50];
            float s = 0.f;
#pragma unroll
            for (int i = 0; i < 50; i++) s = fmaf(hp[i], wp[i * KDIM], s);
            s += __shfl_xor_sync(0xffffffffu, s, 1);
            s += __shfl_xor_sync(0xffffffffu, s, 2);
            if (p == 0) {
                float kk = ftanh(s + S.bk[k]);
                S.key[k] = kk;
                S.kn[k]  = kk / fmaxf(fabsf(kk), EPSF);
            }
        } else if (tid < 4 * KDIM + 8) {      // sigma: 8 threads x 25
            const int p = tid - 4 * KDIM;
            float s = 0.f;
#pragma unroll
            for (int i = 0; i < 25; i++) s = fmaf(S.hsh[p * 25 + i], S.Ws[p * 25 + i], s);
            s += __shfl_xor_sync(0xFFu, s, 4);
            s += __shfl_xor_sync(0xFFu, s, 2);
            s += __shfl_xor_sync(0xFFu, s, 1);
            if (p == 0) S.sig = fsigmoid(s + S.bs);
        }
        __syncthreads();

        float e = 0.f;
        if (tid < NSLOT) {
            const float sg = S.sig;
            const float ww = fmaf(sg, wr, 1.f - sg);
            float n0 = 0.f, n1 = 0.f, n2 = 0.f, n3 = 0.f;
            float d0 = 0.f, d1 = 0.f, d2 = 0.f, d3 = 0.f;
#pragma unroll
            for (int d = 0; d < KDIM; d += 4) {
                M[d]     = fmaf(ww, S.key[d],     M[d]);
                M[d + 1] = fmaf(ww, S.key[d + 1], M[d + 1]);
                M[d + 2] = fmaf(ww, S.key[d + 2], M[d + 2]);
                M[d + 3] = fmaf(ww, S.key[d + 3], M[d + 3]);
                n0 = fmaf(M[d],     M[d],     n0);
                n1 = fmaf(M[d + 1], M[d + 1], n1);
                n2 = fmaf(M[d + 2], M[d + 2], n2);
                n3 = fmaf(M[d + 3], M[d + 3], n3);
                d0 = fmaf(M[d],     S.kn[d],     d0);
                d1 = fmaf(M[d + 1], S.kn[d + 1], d1);
                d2 = fmaf(M[d + 2], S.kn[d + 2], d2);
                d3 = fmaf(M[d + 3], S.kn[d + 3], d3);
            }
            const float ns  = (n0 + n1) + (n2 + n3);      // >= 4e-11, never 0
            const float dot = (d0 + d1) + (d2 + d3);
            e = __expf(dot * rsqrtf(ns));                 // |logit| <= sqrt(40)
            float s = e;
#pragma unroll
            for (int off = 16; off > 0; off >>= 1) s += __shfl_xor_sync(0xffffffffu, s, off);
            if ((tid & 31) == 0) S.wsum[tid >> 5] = s;
        }
        __syncthreads();
        if (tid < NSLOT) {
            float tot = (S.wsum[0] + S.wsum[1]) + (S.wsum[2] + S.wsum[3]);
            wr = __fdividef(e, tot);
        }
    }

    if (tid < NSLOT) {
#pragma unroll
        for (int d = 0; d < KDIM; d++) out[tid * KDIM + d] = M[d];
    }
}

// ---------------- launch ----------------
extern "C" void kernel_launch(void* const* d_in, const int* in_sizes, int n_in,
                              void* d_out, int out_size) {
    const float* x    = (const float*)d_in[0];
    const float* y    = (const float*)d_in[1];
    const float* W_in = (const float*)d_in[2];
    const float* b_in = (const float*)d_in[3];
    const float* W_ih = (const float*)d_in[4];
    const float* W_hh = (const float*)d_in[5];
    const float* b_ih = (const float*)d_in[6];
    const float* b_hh = (const float*)d_in[7];
    const float* W_k  = (const float*)d_in[8];
    const float* b_k  = (const float*)d_in[9];
    const float* W_s  = (const float*)d_in[10];
    const float* b_s  = (const float*)d_in[11];
    // gamma unused: wlu mask is identically 1, wu/gamma cancel out of M_T

    prep_kernel<<<(G4 * FDIM + 255) / 256, 256>>>(W_in, W_ih, b_ih, b_hh);
    gemm1_kernel<<<dim3(FDIM / 64, TSTEPS / 64), 256>>>(x, b_in);
    gemm2_kernel<<<dim3((G4 + 63) / 64, TSTEPS / 64), 256>>>(y);
    fused_kernel<<<2 * CLSZ, 256>>>(W_hh, W_k, b_k, W_s, b_s, (float*)d_out);
}

// round 4
// speedup vs baseline: 1.5647x; 1.5647x over previous
#include <cuda_runtime.h>
#include <cstdint>
#include <math.h>

#define TSTEPS 4096
#define DIN    512
#define FDIM   256
#define HID    200
#define G4     800
#define KDIM   40
#define NSLOT  128
#define EPSF   1e-12f
#define CLSZ   8

// ---------------- scratch (device globals) ----------------
__device__ float g_xs[TSTEPS * FDIM];
__device__ float g_gx[TSTEPS * G4];
__device__ float g_WinT[FDIM * DIN];
__device__ float g_Wx[G4 * FDIM];
__device__ float g_wy[G4];
__device__ float g_bsum[G4];

// ---------------- helpers ----------------
__device__ __forceinline__ float fsigmoid(float x) {
    return __fdividef(1.f, 1.f + __expf(-x));
}
__device__ __forceinline__ float ftanh(float x) {
    float a = fabsf(x);
    float e = __expf(-2.f * a);
    float r = __fdividef(1.f - e, 1.f + e);
    return copysignf(r, x);
}
__device__ __forceinline__ uint32_t smem_u32(const void* p) {
    return (uint32_t)__cvta_generic_to_shared(p);
}
__device__ __forceinline__ uint32_t my_cluster_rank() {
    uint32_t r; asm("mov.u32 %0, %%cluster_ctarank;" : "=r"(r)); return r;
}
__device__ __forceinline__ uint32_t mapa_u32(uint32_t laddr, uint32_t rank) {
    uint32_t r;
    asm("mapa.shared::cluster.u32 %0, %1, %2;" : "=r"(r) : "r"(laddr), "r"(rank));
    return r;
}
__device__ __forceinline__ void cluster_sync_() {
    asm volatile("barrier.cluster.arrive.aligned;" ::: "memory");
    asm volatile("barrier.cluster.wait.aligned;" ::: "memory");
}
__device__ __forceinline__ void dsmem_st_f32(uint32_t raddr, float v) {
    asm volatile("st.shared::cluster.f32 [%0], %1;" :: "r"(raddr), "f"(v) : "memory");
}
// packed fp32x2 FMA: d = a*b + d  (sm_100 FFMA2; ptxas never auto-fuses this)
__device__ __forceinline__ void fma2(unsigned long long& d, unsigned long long a, unsigned long long b) {
    asm("fma.rn.f32x2 %0, %1, %2, %0;" : "+l"(d) : "l"(a), "l"(b));
}
__device__ __forceinline__ float2 unpack2(unsigned long long v) {
    float2 r; asm("mov.b64 {%0, %1}, %2;" : "=f"(r.x), "=f"(r.y) : "l"(v)); return r;
}
__device__ __forceinline__ unsigned long long pack2(float x, float y) {
    unsigned long long v; asm("mov.b64 %0, {%1, %2};" : "=l"(v) : "f"(x), "f"(y)); return v;
}

// ---------------- prep ----------------
__global__ void prep_kernel(const float* __restrict__ W_in, const float* __restrict__ W_ih,
                            const float* __restrict__ b_ih, const float* __restrict__ b_hh) {
    int idx = blockIdx.x * blockDim.x + threadIdx.x;
    if (idx < G4 * FDIM) {
        int n = idx / FDIM, k = idx % FDIM;
        g_Wx[idx] = W_ih[n * (FDIM + 1) + k];
    }
    if (idx < DIN * FDIM) {
        int k = idx / FDIM, n = idx % FDIM;
        g_WinT[n * DIN + k] = W_in[idx];
    }
    if (idx < G4) {
        g_wy[idx]   = W_ih[idx * (FDIM + 1) + FDIM];
        g_bsum[idx] = b_ih[idx] + b_hh[idx];
    }
}

// ---------------- GEMM C = A * B^T ----------------
__device__ __forceinline__ void gemm_nt_body(
    const float* __restrict__ A, const float* __restrict__ B, float* __restrict__ C,
    int M, int N, int K,
    const float* __restrict__ bias, const float* __restrict__ yvec, const float* __restrict__ wy)
{
    __shared__ __align__(16) float As[16][64];
    __shared__ __align__(16) float Bs[16][64];
    const int m0 = blockIdx.y * 64, n0 = blockIdx.x * 64;
    const int tid = threadIdx.x;
    const int tx = tid % 16, ty = tid / 16;
    const int lr = tid / 4, lc4 = (tid % 4) * 4;

    float acc[4][4];
#pragma unroll
    for (int i = 0; i < 4; i++)
#pragma unroll
        for (int j = 0; j < 4; j++) acc[i][j] = 0.f;

    for (int k0 = 0; k0 < K; k0 += 16) {
        float4 av = *reinterpret_cast<const float4*>(A + (size_t)(m0 + lr) * K + k0 + lc4);
        As[lc4 + 0][lr] = av.x; As[lc4 + 1][lr] = av.y;
        As[lc4 + 2][lr] = av.z; As[lc4 + 3][lr] = av.w;
        float4 bv = make_float4(0.f, 0.f, 0.f, 0.f);
        if (n0 + lr < N) bv = *reinterpret_cast<const float4*>(B + (size_t)(n0 + lr) * K + k0 + lc4);
        Bs[lc4 + 0][lr] = bv.x; Bs[lc4 + 1][lr] = bv.y;
        Bs[lc4 + 2][lr] = bv.z; Bs[lc4 + 3][lr] = bv.w;
        __syncthreads();
#pragma unroll
        for (int kk = 0; kk < 16; kk++) {
            float4 a4 = *reinterpret_cast<const float4*>(&As[kk][ty * 4]);
            float4 b4 = *reinterpret_cast<const float4*>(&Bs[kk][tx * 4]);
            float aa[4] = {a4.x, a4.y, a4.z, a4.w};
            float bb[4] = {b4.x, b4.y, b4.z, b4.w};
#pragma unroll
            for (int i = 0; i < 4; i++)
#pragma unroll
                for (int j = 0; j < 4; j++) acc[i][j] = fmaf(aa[i], bb[j], acc[i][j]);
        }
        __syncthreads();
    }
#pragma unroll
    for (int i = 0; i < 4; i++) {
        int m = m0 + ty * 4 + i;
        float yv = 0.f;
        if (yvec) yv = (m == 0) ? 0.f : yvec[m - 1];
#pragma unroll
        for (int j = 0; j < 4; j++) {
            int n = n0 + tx * 4 + j;
            if (n < N) {
                float v = acc[i][j] + (bias ? bias[n] : 0.f);
                if (wy) v = fmaf(yv, wy[n], v);
                C[(size_t)m * N + n] = v;
            }
        }
    }
}

__global__ void __launch_bounds__(256) gemm1_kernel(const float* __restrict__ x,
                                                    const float* __restrict__ b_in) {
    gemm_nt_body(x, g_WinT, g_xs, TSTEPS, FDIM, DIN, b_in, nullptr, nullptr);
}
__global__ void __launch_bounds__(256) gemm2_kernel(const float* __restrict__ y) {
    gemm_nt_body(g_xs, g_Wx, g_gx, TSTEPS, G4, FDIM, g_bsum, y, g_wy);
}

// ---------------- fused kernel shared state ----------------
struct Shm {
    __align__(16) float h[2][HID];         // double-buffered hidden (dsmem broadcast target)
    __align__(16) float Wk[HID * KDIM];    // consumer: W_k
    __align__(8)  float Ws[HID];
    __align__(8)  float bk[KDIM];
    __align__(8)  float key[KDIM];
    __align__(8)  float kn[KDIM];
    float wsum[4];
    float sig, bs;
};

// one MANN+keys step on hidden vector hb (all 256 consumer threads enter)
__device__ __forceinline__ void consume_step(Shm& S, int tid, const float* __restrict__ hb,
                                             unsigned long long* M2, float& wr)
{
    if (tid < 160) {                       // keys: 4 threads per output (warps 0-4 full)
        const int k = tid >> 2, p = tid & 3;
        const float* wp = &S.Wk[(p * 50) * KDIM + k];
        const float* hp = &hb[p * 50];
        float a = 0.f, b = 0.f;
#pragma unroll
        for (int i = 0; i < 50; i += 2) {
            a = fmaf(hp[i],     wp[i * KDIM],       a);
            b = fmaf(hp[i + 1], wp[(i + 1) * KDIM], b);
        }
        float acc = a + b;
        acc += __shfl_xor_sync(0xffffffffu, acc, 1);
        acc += __shfl_xor_sync(0xffffffffu, acc, 2);
        if (p == 0) {
            float kv = ftanh(acc + S.bk[k]);
            S.key[k] = kv;
            S.kn[k]  = kv / fmaxf(fabsf(kv), EPSF);
        }
    } else if (tid < 168) {                // sigma: 8 threads x 25 (warp 5 lanes 0-7)
        const int p = tid - 160;
        float a = 0.f;
#pragma unroll
        for (int i = 0; i < 25; i++) a = fmaf(hb[p * 25 + i], S.Ws[p * 25 + i], a);
        a += __shfl_xor_sync(0xFFu, a, 4);
        a += __shfl_xor_sync(0xFFu, a, 2);
        a += __shfl_xor_sync(0xFFu, a, 1);
        if (p == 0) S.sig = fsigmoid(a + S.bs);
    }
    __syncthreads();

    float e = 0.f;
    if (tid < NSLOT) {
        const float sg = S.sig;
        const float ww = fmaf(sg, wr, 1.f - sg);     // wlu mask == 1 identically
        const unsigned long long ww2 = pack2(ww, ww);
        const unsigned long long* k2  = reinterpret_cast<const unsigned long long*>(S.key);
        const unsigned long long* kn2 = reinterpret_cast<const unsigned long long*>(S.kn);
        unsigned long long n0 = 0, n1 = 0, d0 = 0, d1 = 0;
#pragma unroll
        for (int q = 0; q < 20; q += 2) {
            fma2(M2[q],     ww2, k2[q]);
            fma2(M2[q + 1], ww2, k2[q + 1]);
            fma2(n0, M2[q],     M2[q]);
            fma2(n1, M2[q + 1], M2[q + 1]);
            fma2(d0, M2[q],     kn2[q]);
            fma2(d1, M2[q + 1], kn2[q + 1]);
        }
        float2 na = unpack2(n0), nb = unpack2(n1), da = unpack2(d0), db = unpack2(d1);
        float ns  = (na.x + na.y) + (nb.x + nb.y);   // >= 4e-11, never 0
        float dot = (da.x + da.y) + (db.x + db.y);
        e = __expf(dot * rsqrtf(ns));                // |logit| <= sqrt(40), no max-sub needed
        float s = e;
#pragma unroll
        for (int off = 16; off > 0; off >>= 1) s += __shfl_xor_sync(0xffffffffu, s, off);
        if ((tid & 31) == 0) S.wsum[tid >> 5] = s;
    }
    __syncthreads();
    if (tid < NSLOT) {
        float tot = (S.wsum[0] + S.wsum[1]) + (S.wsum[2] + S.wsum[3]);
        wr = __fdividef(e, tot);
    }
}

__global__ void __cluster_dims__(CLSZ, 1, 1) __launch_bounds__(256, 1)
fused_kernel(const float* __restrict__ W_hh,
             const float* __restrict__ W_k, const float* __restrict__ b_k,
             const float* __restrict__ W_s, const float* __restrict__ b_s,
             float* __restrict__ out)
{
    __shared__ Shm S;
    const int tid = threadIdx.x;
    const uint32_t rank = my_cluster_rank();
    const bool is_consumer = (rank == CLSZ - 1);

    if (tid < HID) { S.h[0][tid] = 0.f; S.h[1][tid] = 0.f; }

    // ---------- producer init ----------
    const int units = is_consumer ? 0 : ((rank < 6) ? 29 : 26);
    const int base  = 29 * (int)rank;           // rank 6 -> 174
    const int nact  = 8 * units;
    const bool act  = tid < nact;
    const int u   = tid >> 3;                    // unit within CTA
    const int sub = tid & 7;                     // 2*gate + cc
    const int g   = sub >> 1;
    const int cc  = sub & 1;
    const int grow = act ? (g * HID + base + u) : 0;

    unsigned long long w[50];
    if (act) {
        const unsigned long long* wp =
            reinterpret_cast<const unsigned long long*>(W_hh + (size_t)grow * HID + cc * 100);
#pragma unroll
        for (int q = 0; q < 50; q++) w[q] = wp[q];
    }
    unsigned mask = 0;
    if (act) {
        int rem = nact - (tid & ~31);
        mask = (rem >= 32) ? 0xffffffffu : ((1u << rem) - 1u);
    }
    uint32_t r_h[CLSZ];
    if (act && sub == 0) {
        uint32_t hA = smem_u32(&S.h[0][0]);
#pragma unroll
        for (int p = 0; p < CLSZ; p++) r_h[p] = mapa_u32(hA, (uint32_t)p);
    }

    // ---------- consumer init ----------
    unsigned long long M2[20];
    float wr = 0.f;
    if (is_consumer) {
        for (int i = tid; i < HID * KDIM; i += 256) S.Wk[i] = W_k[i];
        for (int i = tid; i < HID; i += 256) S.Ws[i] = W_s[i];
        if (tid < KDIM) S.bk[tid] = b_k[tid];
        if (tid == 0)   S.bs = b_s[0];
        if (tid < NSLOT) {
#pragma unroll
            for (int q = 0; q < 20; q++) M2[q] = pack2(1e-6f, 1e-6f);
            wr = (tid == 0) ? 1.f : 0.f;
        }
    }

    __syncthreads();
    cluster_sync_();

    float cst = 0.f;
    float gxv = (act && cc == 0) ? g_gx[grow] : 0.f;

    for (int t = 0; t < TSTEPS; t++) {
        if (!is_consumer) {
            const int buf = t & 1, bw = buf ^ 1;
            float gxn = 0.f;
            if (act && cc == 0) {
                int tn = (t + 1 < TSTEPS) ? (t + 1) : t;   // prefetch next gx (latency under FMA)
                gxn = g_gx[(size_t)tn * G4 + grow];
            }
            if (act) {
                const unsigned long long* h8 =
                    reinterpret_cast<const unsigned long long*>(&S.h[buf][cc * 100]);
                unsigned long long a0 = 0, a1 = 0, a2 = 0, a3 = 0;
#pragma unroll
                for (int q = 0; q < 48; q += 4) {
                    fma2(a0, w[q],     h8[q]);
                    fma2(a1, w[q + 1], h8[q + 1]);
                    fma2(a2, w[q + 2], h8[q + 2]);
                    fma2(a3, w[q + 3], h8[q + 3]);
                }
                fma2(a0, w[48], h8[48]);
                fma2(a1, w[49], h8[49]);
                float2 f0 = unpack2(a0), f1 = unpack2(a1), f2 = unpack2(a2), f3 = unpack2(a3);
                float dsum = ((f0.x + f0.y) + (f1.x + f1.y)) + ((f2.x + f2.y) + (f3.x + f3.y));
                dsum += __shfl_xor_sync(mask, dsum, 1);          // combine the two k-halves
                float av = 0.f;
                if (cc == 0) {
                    float gs = dsum + gxv;
                    av = (g == 2) ? ftanh(gs) : fsigmoid(gs);    // gate activation on even lanes
                }
                float fv = __shfl_down_sync(mask, av, 2);
                float gv = __shfl_down_sync(mask, av, 4);
                float ov = __shfl_down_sync(mask, av, 6);
                if (sub == 0) {
                    cst = fv * cst + av * gv;
                    float h = ov * ftanh(cst);
                    const uint32_t off = (uint32_t)(bw * HID + base + u) * 4u;
#pragma unroll
                    for (int p = 0; p < CLSZ; p++) dsmem_st_f32(r_h[p] + off, h);
                }
            }
            gxv = gxn;
        } else {
            if (t >= 1) consume_step(S, tid, &S.h[t & 1][0], M2, wr);   // process h_{t-1}
        }
        cluster_sync_();   // release writes of h_t; acquire for next step's reads
    }

    if (is_consumer) {
        consume_step(S, tid, &S.h[0][0], M2, wr);   // tail: h_4095 (in buffer 0)
        if (tid < NSLOT) {
#pragma unroll
            for (int q = 0; q < 20; q++) {
                float2 v = unpack2(M2[q]);
                out[tid * KDIM + 2 * q]     = v.x;
                out[tid * KDIM + 2 * q + 1] = v.y;
            }
        }
    }
}

// ---------------- launch ----------------
extern "C" void kernel_launch(void* const* d_in, const int* in_sizes, int n_in,
                              void* d_out, int out_size) {
    const float* x    = (const float*)d_in[0];
    const float* y    = (const float*)d_in[1];
    const float* W_in = (const float*)d_in[2];
    const float* b_in = (const float*)d_in[3];
    const float* W_ih = (const float*)d_in[4];
    const float* W_hh = (const float*)d_in[5];
    const float* b_ih = (const float*)d_in[6];
    const float* b_hh = (const float*)d_in[7];
    const float* W_k  = (const float*)d_in[8];
    const float* b_k  = (const float*)d_in[9];
    const float* W_s  = (const float*)d_in[10];
    const float* b_s  = (const float*)d_in[11];
    // gamma (d_in[12]) provably unused: wlu mask is identically 1, wu/gamma cancel

    prep_kernel<<<(G4 * FDIM + 255) / 256, 256>>>(W_in, W_ih, b_ih, b_hh);
    gemm1_kernel<<<dim3(FDIM / 64, TSTEPS / 64), 256>>>(x, b_in);
    gemm2_kernel<<<dim3((G4 + 63) / 64, TSTEPS / 64), 256>>>(y);
    fused_kernel<<<CLSZ, 256>>>(W_hh, W_k, b_k, W_s, b_s, (float*)d_out);
}